// round 10
// baseline (speedup 1.0000x reference)
#include <cuda_runtime.h>
#include <cuda_bf16.h>
#include <math.h>
#include <stdint.h>

#define BDIM 64
#define SDIM 2048
#define IDIM 512
#define HDIM 512

// ---------------- device scratch (no cudaMalloc allowed) -------------------
__device__ float g_hb[BDIM * HDIM];
__device__ float g_att[BDIM * SDIM];
__device__ float g_cbar[BDIM * IDIM];
__device__ int   g_mask_is_byte;

__device__ __nv_bfloat16 g_wc_hi[HDIM * IDIM];
__device__ __nv_bfloat16 g_wc_lo[HDIM * IDIM];

// ---------------- PTX helpers (sm_80-level only) ----------------------------
__device__ __forceinline__ uint32_t smem_u32(const void* p) {
    uint32_t a;
    asm("{ .reg .u64 t; cvta.to.shared.u64 t, %1; cvt.u32.u64 %0, t; }" : "=r"(a) : "l"(p));
    return a;
}
#define CP16(dst, src) asm volatile("cp.async.cg.shared.global [%0], [%1], 16;" :: "r"(dst), "l"(src))
#define CP_COMMIT()    asm volatile("cp.async.commit_group;" ::: "memory")
#define CP_WAIT(n)     asm volatile("cp.async.wait_group %0;" :: "n"(n) : "memory")

#define LDSM4(r, a)                                                           \
    asm volatile("ldmatrix.sync.aligned.m8n8.x4.shared.b16 {%0,%1,%2,%3}, [%4];" \
        : "=r"((r)[0]), "=r"((r)[1]), "=r"((r)[2]), "=r"((r)[3]) : "r"(a))

#define MMA16816(c, a, b0, b1)                                                \
    asm volatile("mma.sync.aligned.m16n8k16.row.col.f32.bf16.bf16.f32 "       \
        "{%0,%1,%2,%3},{%4,%5,%6,%7},{%8,%9},{%0,%1,%2,%3};"                  \
        : "+f"((c)[0]), "+f"((c)[1]), "+f"((c)[2]), "+f"((c)[3])              \
        : "r"((a)[0]), "r"((a)[1]), "r"((a)[2]), "r"((a)[3]), "r"(b0), "r"(b1))

__device__ __forceinline__ uint32_t pack_bf16x2(float a, float b) {
    __nv_bfloat162 t(__float2bfloat16(a), __float2bfloat16(b));
    return *reinterpret_cast<uint32_t*>(&t);
}

// ---------------------------------------------------------------------------
// K0: detect mask storage (int32 vs uint8)
// ---------------------------------------------------------------------------
__global__ void k0_detect(const unsigned char* __restrict__ mraw) {
    __shared__ int found;
    if (threadIdx.x == 0) found = 0;
    __syncthreads();
    int acc = 0;
    for (int i = threadIdx.x; i < 4096; i += 256)
        if ((i & 3) != 0 && mraw[i] != 0) acc = 1;
    if (acc) atomicOr(&found, 1);
    __syncthreads();
    if (threadIdx.x == 0) g_mask_is_byte = found;
}

// ---------------------------------------------------------------------------
// Kc: fp32 -> (hi, lo) bf16 split (Wc only; context converted inside k2)
// ---------------------------------------------------------------------------
__global__ void k_conv(const float* __restrict__ src, __nv_bfloat16* __restrict__ hi,
                       __nv_bfloat16* __restrict__ lo, int n4) {
    int i = blockIdx.x * blockDim.x + threadIdx.x;
    if (i >= n4) return;
    float4 v = ((const float4*)src)[i];
    __nv_bfloat16 h0 = __float2bfloat16(v.x), h1 = __float2bfloat16(v.y);
    __nv_bfloat16 h2 = __float2bfloat16(v.z), h3 = __float2bfloat16(v.w);
    __nv_bfloat16 l0 = __float2bfloat16(v.x - __bfloat162float(h0));
    __nv_bfloat16 l1 = __float2bfloat16(v.y - __bfloat162float(h1));
    __nv_bfloat16 l2 = __float2bfloat16(v.z - __bfloat162float(h2));
    __nv_bfloat16 l3 = __float2bfloat16(v.w - __bfloat162float(h3));
    __nv_bfloat162* hp = (__nv_bfloat162*)hi;
    __nv_bfloat162* lp = (__nv_bfloat162*)lo;
    hp[i * 2 + 0] = __nv_bfloat162(h0, h1);
    hp[i * 2 + 1] = __nv_bfloat162(h2, h3);
    lp[i * 2 + 0] = __nv_bfloat162(l0, l1);
    lp[i * 2 + 1] = __nv_bfloat162(l2, l3);
}

// ---------------------------------------------------------------------------
// K1: hb = inp@Wl.T + bl + bc ; zero g_cbar and g_att (warp-per-row, coalesced)
// ---------------------------------------------------------------------------
__global__ void __launch_bounds__(256) k1_hb(const float* __restrict__ inp,
                                             const float* __restrict__ Wl,
                                             const float* __restrict__ bl,
                                             const float* __restrict__ bc) {
    __shared__ float sin[IDIM];
    int b  = blockIdx.x >> 2;
    int hq = blockIdx.x & 3;
    int tid = threadIdx.x;
    int wid = tid >> 5, lane = tid & 31;

    sin[tid] = inp[b * IDIM + tid];
    sin[tid + 256] = inp[b * IDIM + tid + 256];
    g_att[b * SDIM + hq * 512 + tid * 2 + 0] = 0.0f;
    g_att[b * SDIM + hq * 512 + tid * 2 + 1] = 0.0f;
    if (tid < 128) g_cbar[b * IDIM + hq * 128 + tid] = 0.0f;
    __syncthreads();

    const float4* s4 = (const float4*)sin;
    #pragma unroll 1
    for (int r = wid; r < 128; r += 8) {
        int h = hq * 128 + r;
        const float4* w4 = (const float4*)(Wl + (size_t)h * IDIM);
        float acc = 0.0f;
        #pragma unroll
        for (int j = 0; j < 4; j++) {
            float4 w = w4[lane + 32 * j];
            float4 s = s4[lane + 32 * j];
            acc += w.x * s.x + w.y * s.y + w.z * s.z + w.w * s.w;
        }
        #pragma unroll
        for (int o = 16; o > 0; o >>= 1) acc += __shfl_xor_sync(0xffffffffu, acc, o);
        if (lane == 0) g_hb[b * HDIM + h] = acc + bl[h] + bc[h];
    }
}

// ---------------------------------------------------------------------------
// K2: bf16 hi/lo-split GEMM + tanh + V reduction.
// In-kernel fp32->bf16 split of context (LDG -> regs -> STS), R7's 3-stage
// schedule: loads for chunk i+2 at top of iter i, CP_WAIT(2), two syncs.
// Stage (64KB): Ahi 16K | Alo 16K | Bhi 16K | Blo 16K;  3 stages = 192KB.
// grid = B * 16(stile) * 4(htile) = 4096 CTAs, 256 threads.
// ---------------------------------------------------------------------------
#define ST_AH 0u
#define ST_AL 16384u
#define ST_BH 32768u
#define ST_BL 49152u
#define STAGE_BYTES 65536u
#define SMEM_K2 (3 * STAGE_BYTES)

__global__ void __launch_bounds__(256, 1) k2_att_mma(const float* __restrict__ context,
                                                     const float* __restrict__ Vv) {
    extern __shared__ char smem[];
    __shared__ float sV[128], sHB[128], attred[128];
    uint32_t sb = smem_u32(smem);

    int tid  = threadIdx.x;
    int wid  = tid >> 5;
    int lane = tid & 31;
    int g    = lane >> 2;
    int tg   = lane & 3;
    int warp_m = wid & 1;
    int warp_n = wid >> 1;

    int bx = blockIdx.x;
    int b     = bx >> 6;
    int stile = (bx >> 2) & 15;
    int htile = bx & 3;
    int s0    = stile * 128;
    int hbase = htile * 128;
    int bb    = b * SDIM;

    if (tid < 128) {
        sV[tid]  = Vv[hbase + tid];
        sHB[tid] = g_hb[b * HDIM + hbase + tid];
        attred[tid] = 0.0f;
    }

    // A loader: thread -> (row ar, half-row of 32 fp32)
    int ar    = tid >> 1;
    int ahalf = tid & 1;
    const uint4* actx = (const uint4*)(context + (size_t)(bb + s0 + ar) * IDIM + ahalf * 32);

    uint4 regs[8];
    auto ldgA = [&](int kc) {
        const uint4* src = actx + kc * 16;
        #pragma unroll
        for (int j = 0; j < 8; j++) regs[j] = src[j];
    };
    auto stsA = [&](uint32_t stage_off) {   // byte offset of stage within smem[]
        #pragma unroll
        for (int q = 0; q < 4; q++) {
            uint4 ra = regs[q * 2], rb = regs[q * 2 + 1];
            float f0 = __uint_as_float(ra.x), f1 = __uint_as_float(ra.y);
            float f2 = __uint_as_float(ra.z), f3 = __uint_as_float(ra.w);
            float f4 = __uint_as_float(rb.x), f5 = __uint_as_float(rb.y);
            float f6 = __uint_as_float(rb.z), f7 = __uint_as_float(rb.w);
            uint4 hv, lv;
            hv.x = pack_bf16x2(f0, f1); hv.y = pack_bf16x2(f2, f3);
            hv.z = pack_bf16x2(f4, f5); hv.w = pack_bf16x2(f6, f7);
            float r0 = f0 - __bfloat162float(__float2bfloat16(f0));
            float r1 = f1 - __bfloat162float(__float2bfloat16(f1));
            float r2 = f2 - __bfloat162float(__float2bfloat16(f2));
            float r3 = f3 - __bfloat162float(__float2bfloat16(f3));
            float r4 = f4 - __bfloat162float(__float2bfloat16(f4));
            float r5 = f5 - __bfloat162float(__float2bfloat16(f5));
            float r6 = f6 - __bfloat162float(__float2bfloat16(f6));
            float r7 = f7 - __bfloat162float(__float2bfloat16(f7));
            lv.x = pack_bf16x2(r0, r1); lv.y = pack_bf16x2(r2, r3);
            lv.z = pack_bf16x2(r4, r5); lv.w = pack_bf16x2(r6, r7);
            uint32_t off = ((uint32_t)(ar * 128 + ahalf * 64 + q * 16))
                         ^ ((uint32_t)(ar & 7) << 4);
            *(uint4*)(smem + stage_off + ST_AH + off) = hv;
            *(uint4*)(smem + stage_off + ST_AL + off) = lv;
        }
    };
    // B loader via cp.async (preconverted Wc hi/lo)
    auto loadB = [&](int kc, uint32_t stage_base) {  // stage_base = sb + offset
        int k0 = kc * 64;
        #pragma unroll
        for (int j = 0; j < 8; j++) {
            int idx = j * 256 + tid;
            int sg  = idx >> 10;
            int rem = idx & 1023;
            int r = rem >> 3, c = rem & 7;
            const __nv_bfloat16* src = (sg ? g_wc_lo : g_wc_hi)
                + ((size_t)(hbase + r) * IDIM + k0 + c * 8);
            uint32_t o = (uint32_t)(r * 128 + c * 16);
            CP16(stage_base + ST_BH + (uint32_t)sg * 16384u
                 + (o ^ (uint32_t)((r & 7) << 4)), src);
        }
        CP_COMMIT();
    };

    // ldmatrix address components (128B rows, XOR swizzle)
    int arow  = warp_m * 64 + (lane & 15);
    uint32_t akoff = (uint32_t)(lane & 16);
    uint32_t axor  = (uint32_t)((lane & 7) << 4);
    int brow  = (lane & 7) + ((lane & 16) >> 1);
    uint32_t bkoff = (uint32_t)(((lane >> 3) & 1) * 16);

    uint32_t aoff[4], boff[2];
    #pragma unroll
    for (int t = 0; t < 4; t++) aoff[t] = (uint32_t)((arow + t * 16) * 128) + akoff;
    #pragma unroll
    for (int p = 0; p < 2; p++) boff[p] = (uint32_t)((warp_n * 32 + p * 16 + brow) * 128) + bkoff;

    float acc[4][4][4];
    #pragma unroll
    for (int t = 0; t < 4; t++)
        #pragma unroll
        for (int n = 0; n < 4; n++)
            #pragma unroll
            for (int c = 0; c < 4; c++) acc[t][n][c] = 0.0f;

    // ---- prologue: stage A(0), A(1) via LDG->STS; B(0), B(1) via cp.async;
    //      preload A(2) into regs for iter 0.
    ldgA(0); stsA(0u * STAGE_BYTES);
    ldgA(1); stsA(1u * STAGE_BYTES);
    loadB(0, sb + 0u * STAGE_BYTES);
    loadB(1, sb + 1u * STAGE_BYTES);
    ldgA(2);

    #pragma unroll 1
    for (int i = 0; i < 8; i++) {
        // top-of-iter: stage chunk i+2 (stage (i+2)%3, readers done at iter i-1)
        if (i + 2 < 8) {
            uint32_t stw = (uint32_t)((i + 2) % 3) * STAGE_BYTES;
            stsA(stw);
            loadB(i + 2, sb + stw);
            if (i + 3 < 8) ldgA(i + 3);
        }
        if (i + 2 < 8)      { CP_WAIT(2); }
        else if (i + 1 < 8) { CP_WAIT(1); }
        else                { CP_WAIT(0); }
        __syncthreads();

        uint32_t stb = sb + (uint32_t)(i % 3) * STAGE_BYTES;
        uint32_t AH = stb + ST_AH, AL = stb + ST_AL;
        uint32_t BH = stb + ST_BH, BL = stb + ST_BL;

        #pragma unroll
        for (int q = 0; q < 4; q++) {
            uint32_t qb = (uint32_t)(q * 32);
            uint32_t aH[4][4], aL[4][4], bH[2][4], bL[2][4];
            #pragma unroll
            for (int t = 0; t < 4; t++) {
                LDSM4(aH[t], AH + ((aoff[t] + qb) ^ axor));
                LDSM4(aL[t], AL + ((aoff[t] + qb) ^ axor));
            }
            #pragma unroll
            for (int p = 0; p < 2; p++) {
                LDSM4(bH[p], BH + ((boff[p] + qb) ^ axor));
                LDSM4(bL[p], BL + ((boff[p] + qb) ^ axor));
            }
            #pragma unroll
            for (int t = 0; t < 4; t++)
                #pragma unroll
                for (int nt = 0; nt < 4; nt++) {
                    int p  = nt >> 1;
                    int r0 = (nt & 1) * 2;
                    MMA16816(acc[t][nt], aH[t], bH[p][r0], bH[p][r0 + 1]);
                    MMA16816(acc[t][nt], aH[t], bL[p][r0], bL[p][r0 + 1]);
                    MMA16816(acc[t][nt], aL[t], bH[p][r0], bH[p][r0 + 1]);
                }
        }
        __syncthreads();
    }

    // ---- epilogue: att[s] += sum_h V[h]*tanh(acc + hb[h])
    float rowsum[8];
    #pragma unroll
    for (int r = 0; r < 8; r++) rowsum[r] = 0.0f;
    #pragma unroll
    for (int t = 0; t < 4; t++) {
        #pragma unroll
        for (int nt = 0; nt < 4; nt++) {
            int hh = warp_n * 32 + nt * 8 + tg * 2;
            float v0 = sV[hh], v1 = sV[hh + 1];
            float h0 = sHB[hh], h1 = sHB[hh + 1];
            float* c = acc[t][nt];
            rowsum[t * 2 + 0] += v0 * tanhf(c[0] + h0) + v1 * tanhf(c[1] + h1);
            rowsum[t * 2 + 1] += v0 * tanhf(c[2] + h0) + v1 * tanhf(c[3] + h1);
        }
    }
    #pragma unroll
    for (int r = 0; r < 8; r++) {
        float s = rowsum[r];
        s += __shfl_xor_sync(0xffffffffu, s, 1);
        s += __shfl_xor_sync(0xffffffffu, s, 2);
        if (tg == 0) {
            int row = warp_m * 64 + (r >> 1) * 16 + (r & 1) * 8 + g;
            atomicAdd(&attred[row], s);
        }
    }
    __syncthreads();
    if (tid < 128) atomicAdd(&g_att[b * SDIM + s0 + tid], attred[tid]);
}

// ---------------------------------------------------------------------------
// K3: masked softmax over S per batch -> alpha
// ---------------------------------------------------------------------------
__device__ __forceinline__ bool mask_at(const unsigned char* m, int idx, int is_byte) {
    if (is_byte) return m[idx] != 0;
    return ((const int*)m)[idx] != 0;
}

__global__ void k3_softmax(const unsigned char* __restrict__ mraw,
                           float* __restrict__ alpha) {
    __shared__ float red[256];
    int b = blockIdx.x;
    int tid = threadIdx.x;
    int is_byte = g_mask_is_byte;
    const float NEG_INF = __int_as_float(0xff800000);

    float lmax = NEG_INF;
    for (int s = tid; s < SDIM; s += 256)
        if (!mask_at(mraw, b * SDIM + s, is_byte))
            lmax = fmaxf(lmax, g_att[b * SDIM + s]);
    red[tid] = lmax;
    __syncthreads();
    for (int o = 128; o > 0; o >>= 1) {
        if (tid < o) red[tid] = fmaxf(red[tid], red[tid + o]);
        __syncthreads();
    }
    float smax = red[0];
    __syncthreads();

    float lsum = 0.0f;
    for (int s = tid; s < SDIM; s += 256) {
        float e = 0.0f;
        if (!mask_at(mraw, b * SDIM + s, is_byte))
            e = expf(g_att[b * SDIM + s] - smax);
        alpha[b * SDIM + s] = e;
        lsum += e;
    }
    red[tid] = lsum;
    __syncthreads();
    for (int o = 128; o > 0; o >>= 1) {
        if (tid < o) red[tid] += red[tid + o];
        __syncthreads();
    }
    float inv = 1.0f / red[0];
    __syncthreads();

    for (int s = tid; s < SDIM; s += 256)
        alpha[b * SDIM + s] *= inv;
}

// ---------------------------------------------------------------------------
// K4: cbar[b,i] = sum_s alpha[b,s] * context[b,s,i]
// ---------------------------------------------------------------------------
__global__ void k4_cbar(const float* __restrict__ context,
                        const float* __restrict__ alpha) {
    __shared__ float sal[128];
    int b  = blockIdx.y;
    int s0 = blockIdx.x * 128;
    int i  = threadIdx.x;
    if (i < 128) sal[i] = alpha[b * SDIM + s0 + i];
    __syncthreads();
    const float* cp = context + (size_t)b * SDIM * IDIM + (size_t)s0 * IDIM + i;
    float acc = 0.0f;
    #pragma unroll 4
    for (int s = 0; s < 128; s++) acc += sal[s] * cp[(size_t)s * IDIM];
    atomicAdd(&g_cbar[b * IDIM + i], acc);
}

// ---------------------------------------------------------------------------
// K5: hidden = Wc @ cbar + bc  (coalesced warp-per-row)
// ---------------------------------------------------------------------------
__global__ void __launch_bounds__(256) k5_out(const float* __restrict__ Wc,
                                              const float* __restrict__ bc,
                                              float* __restrict__ out) {
    __shared__ float sc[IDIM];
    int b  = blockIdx.x >> 2;
    int hq = blockIdx.x & 3;
    int tid = threadIdx.x;
    int wid = tid >> 5, lane = tid & 31;

    sc[tid] = g_cbar[b * IDIM + tid];
    sc[tid + 256] = g_cbar[b * IDIM + tid + 256];
    __syncthreads();

    const float4* s4 = (const float4*)sc;
    #pragma unroll 1
    for (int r = wid; r < 128; r += 8) {
        int h = hq * 128 + r;
        const float4* w4 = (const float4*)(Wc + (size_t)h * IDIM);
        float acc = 0.0f;
        #pragma unroll
        for (int j = 0; j < 4; j++) {
            float4 w = w4[lane + 32 * j];
            float4 s = s4[lane + 32 * j];
            acc += w.x * s.x + w.y * s.y + w.z * s.z + w.w * s.w;
        }
        #pragma unroll
        for (int o = 16; o > 0; o >>= 1) acc += __shfl_xor_sync(0xffffffffu, acc, o);
        if (lane == 0) out[b * HDIM + h] = acc + bc[h];
    }
}

// ---------------------------------------------------------------------------
extern "C" void kernel_launch(void* const* d_in, const int* in_sizes, int n_in,
                              void* d_out, int out_size) {
    const float* inp          = (const float*)d_in[0];
    const float* context      = (const float*)d_in[1];
    const unsigned char* mraw = (const unsigned char*)d_in[2];
    const float* Wl           = (const float*)d_in[3];
    const float* bl           = (const float*)d_in[4];
    const float* Wc           = (const float*)d_in[5];
    const float* bc           = (const float*)d_in[6];
    const float* Vv           = (const float*)d_in[7];

    float* out    = (float*)d_out;
    float* hidden = out;                   // [B, HID]
    float* alpha  = out + BDIM * HDIM;     // [B, S]

    cudaFuncSetAttribute(k2_att_mma, cudaFuncAttributeMaxDynamicSharedMemorySize, SMEM_K2);

    __nv_bfloat16 *wc_hi, *wc_lo;
    cudaGetSymbolAddress((void**)&wc_hi, g_wc_hi);
    cudaGetSymbolAddress((void**)&wc_lo, g_wc_lo);

    k0_detect<<<1, 256>>>(mraw);
    int n4w = HDIM * IDIM / 4;
    k_conv<<<n4w / 256, 256>>>(Wc, wc_hi, wc_lo, n4w);
    k1_hb<<<BDIM * 4, 256>>>(inp, Wl, bl, bc);
    k2_att_mma<<<BDIM * 16 * 4, 256, SMEM_K2>>>(context, Vv);
    k3_softmax<<<BDIM, 256>>>(mraw, alpha);
    k4_cbar<<<dim3(SDIM / 128, BDIM), 512>>>(context, alpha);
    k5_out<<<BDIM * 4, 256>>>(Wc, bc, hidden);
}

// round 11
// speedup vs baseline: 1.1833x; 1.1833x over previous
#include <cuda_runtime.h>
#include <cuda_bf16.h>
#include <math.h>
#include <stdint.h>

#define BDIM 64
#define SDIM 2048
#define IDIM 512
#define HDIM 512

// ---------------- device scratch (no cudaMalloc allowed) -------------------
__device__ float g_hb[BDIM * HDIM];
__device__ float g_att[BDIM * SDIM];
__device__ float g_cbar[BDIM * IDIM];
__device__ int   g_mask_is_byte;

__device__ __nv_bfloat16 g_wc_hi[HDIM * IDIM];
__device__ __nv_bfloat16 g_wc_lo[HDIM * IDIM];

// ---------------- PTX helpers (sm_80-level only) ----------------------------
__device__ __forceinline__ uint32_t smem_u32(const void* p) {
    uint32_t a;
    asm("{ .reg .u64 t; cvta.to.shared.u64 t, %1; cvt.u32.u64 %0, t; }" : "=r"(a) : "l"(p));
    return a;
}
#define CP16(dst, src) asm volatile("cp.async.cg.shared.global [%0], [%1], 16;" :: "r"(dst), "l"(src))
#define CP_COMMIT()    asm volatile("cp.async.commit_group;" ::: "memory")
#define CP_WAIT(n)     asm volatile("cp.async.wait_group %0;" :: "n"(n) : "memory")

#define LDSM4(r, a)                                                           \
    asm volatile("ldmatrix.sync.aligned.m8n8.x4.shared.b16 {%0,%1,%2,%3}, [%4];" \
        : "=r"((r)[0]), "=r"((r)[1]), "=r"((r)[2]), "=r"((r)[3]) : "r"(a))

#define MMA16816(c, a, b0, b1)                                                \
    asm volatile("mma.sync.aligned.m16n8k16.row.col.f32.bf16.bf16.f32 "       \
        "{%0,%1,%2,%3},{%4,%5,%6,%7},{%8,%9},{%0,%1,%2,%3};"                  \
        : "+f"((c)[0]), "+f"((c)[1]), "+f"((c)[2]), "+f"((c)[3])              \
        : "r"((a)[0]), "r"((a)[1]), "r"((a)[2]), "r"((a)[3]), "r"(b0), "r"(b1))

__device__ __forceinline__ uint32_t pack_bf16x2(float a, float b) {
    __nv_bfloat162 t(__float2bfloat16(a), __float2bfloat16(b));
    return *reinterpret_cast<uint32_t*>(&t);
}

// ---------------------------------------------------------------------------
// K0: detect mask storage (int32 vs uint8)
// ---------------------------------------------------------------------------
__global__ void k0_detect(const unsigned char* __restrict__ mraw) {
    __shared__ int found;
    if (threadIdx.x == 0) found = 0;
    __syncthreads();
    int acc = 0;
    for (int i = threadIdx.x; i < 4096; i += 256)
        if ((i & 3) != 0 && mraw[i] != 0) acc = 1;
    if (acc) atomicOr(&found, 1);
    __syncthreads();
    if (threadIdx.x == 0) g_mask_is_byte = found;
}

// ---------------------------------------------------------------------------
// Kc: fp32 -> (hi, lo) bf16 split (Wc only; context converted inside k2)
// ---------------------------------------------------------------------------
__global__ void k_conv(const float* __restrict__ src, __nv_bfloat16* __restrict__ hi,
                       __nv_bfloat16* __restrict__ lo, int n4) {
    int i = blockIdx.x * blockDim.x + threadIdx.x;
    if (i >= n4) return;
    float4 v = ((const float4*)src)[i];
    __nv_bfloat16 h0 = __float2bfloat16(v.x), h1 = __float2bfloat16(v.y);
    __nv_bfloat16 h2 = __float2bfloat16(v.z), h3 = __float2bfloat16(v.w);
    __nv_bfloat16 l0 = __float2bfloat16(v.x - __bfloat162float(h0));
    __nv_bfloat16 l1 = __float2bfloat16(v.y - __bfloat162float(h1));
    __nv_bfloat16 l2 = __float2bfloat16(v.z - __bfloat162float(h2));
    __nv_bfloat16 l3 = __float2bfloat16(v.w - __bfloat162float(h3));
    __nv_bfloat162* hp = (__nv_bfloat162*)hi;
    __nv_bfloat162* lp = (__nv_bfloat162*)lo;
    hp[i * 2 + 0] = __nv_bfloat162(h0, h1);
    hp[i * 2 + 1] = __nv_bfloat162(h2, h3);
    lp[i * 2 + 0] = __nv_bfloat162(l0, l1);
    lp[i * 2 + 1] = __nv_bfloat162(l2, l3);
}

// ---------------------------------------------------------------------------
// K1: hb = inp@Wl.T + bl + bc ; zero g_cbar and g_att (warp-per-row, coalesced)
// ---------------------------------------------------------------------------
__global__ void __launch_bounds__(256) k1_hb(const float* __restrict__ inp,
                                             const float* __restrict__ Wl,
                                             const float* __restrict__ bl,
                                             const float* __restrict__ bc) {
    __shared__ float sin[IDIM];
    int b  = blockIdx.x >> 2;
    int hq = blockIdx.x & 3;
    int tid = threadIdx.x;
    int wid = tid >> 5, lane = tid & 31;

    sin[tid] = inp[b * IDIM + tid];
    sin[tid + 256] = inp[b * IDIM + tid + 256];
    g_att[b * SDIM + hq * 512 + tid * 2 + 0] = 0.0f;
    g_att[b * SDIM + hq * 512 + tid * 2 + 1] = 0.0f;
    if (tid < 128) g_cbar[b * IDIM + hq * 128 + tid] = 0.0f;
    __syncthreads();

    const float4* s4 = (const float4*)sin;
    #pragma unroll 1
    for (int r = wid; r < 128; r += 8) {
        int h = hq * 128 + r;
        const float4* w4 = (const float4*)(Wl + (size_t)h * IDIM);
        float acc = 0.0f;
        #pragma unroll
        for (int j = 0; j < 4; j++) {
            float4 w = w4[lane + 32 * j];
            float4 s = s4[lane + 32 * j];
            acc += w.x * s.x + w.y * s.y + w.z * s.z + w.w * s.w;
        }
        #pragma unroll
        for (int o = 16; o > 0; o >>= 1) acc += __shfl_xor_sync(0xffffffffu, acc, o);
        if (lane == 0) g_hb[b * HDIM + h] = acc + bl[h] + bc[h];
    }
}

// ---------------------------------------------------------------------------
// K2: bf16 hi/lo-split GEMM + tanh + V reduction.
// In-kernel fp32->bf16 split of context with COALESCED LDG (nL=4/instr):
// thread -> (row = tid>>4, 16B chunk = tid&15); warp reads 2 rows x 256B
// contiguous. 3-stage schedule (loads for chunk i+2 at top of iter i).
// Stage (64KB): Ahi 16K | Alo 16K | Bhi 16K | Blo 16K;  3 stages = 192KB.
// grid = B * 16(stile) * 4(htile) = 4096 CTAs, 256 threads.
// ---------------------------------------------------------------------------
#define ST_AH 0u
#define ST_AL 16384u
#define ST_BH 32768u
#define ST_BL 49152u
#define STAGE_BYTES 65536u
#define SMEM_K2 (3 * STAGE_BYTES)

__global__ void __launch_bounds__(256, 1) k2_att_mma(const float* __restrict__ context,
                                                     const float* __restrict__ Vv) {
    extern __shared__ char smem[];
    __shared__ float sV[128], sHB[128], attred[128];
    uint32_t sb = smem_u32(smem);

    int tid  = threadIdx.x;
    int wid  = tid >> 5;
    int lane = tid & 31;
    int g    = lane >> 2;
    int tg   = lane & 3;
    int warp_m = wid & 1;
    int warp_n = wid >> 1;

    int bx = blockIdx.x;
    int b     = bx >> 6;
    int stile = (bx >> 2) & 15;
    int htile = bx & 3;
    int s0    = stile * 128;
    int hbase = htile * 128;
    int bb    = b * SDIM;

    if (tid < 128) {
        sV[tid]  = Vv[hbase + tid];
        sHB[tid] = g_hb[b * HDIM + hbase + tid];
        attred[tid] = 0.0f;
    }

    // A loader: COALESCED. row = tid>>4 (+j*16), 16B chunk = tid&15.
    int arow2 = tid >> 4;      // 0..15
    int ac    = tid & 15;      // 16B chunk within 64-float chunk-row
    const uint4* actx = (const uint4*)context
        + (size_t)(bb + s0 + arow2) * (IDIM / 4) + ac;

    uint4 regs[8];
    auto ldgA = [&](int kc) {
        const uint4* src = actx + kc * 16;
        #pragma unroll
        for (int j = 0; j < 8; j++) regs[j] = src[(size_t)j * 16 * (IDIM / 4)];
    };
    auto stsA = [&](uint32_t stage_off) {   // byte offset of stage within smem[]
        #pragma unroll
        for (int j = 0; j < 8; j++) {
            uint4 r4 = regs[j];
            float f0 = __uint_as_float(r4.x), f1 = __uint_as_float(r4.y);
            float f2 = __uint_as_float(r4.z), f3 = __uint_as_float(r4.w);
            uint2 hv, lv;
            hv.x = pack_bf16x2(f0, f1); hv.y = pack_bf16x2(f2, f3);
            float r0 = f0 - __bfloat162float(__float2bfloat16(f0));
            float r1 = f1 - __bfloat162float(__float2bfloat16(f1));
            float r2 = f2 - __bfloat162float(__float2bfloat16(f2));
            float r3 = f3 - __bfloat162float(__float2bfloat16(f3));
            lv.x = pack_bf16x2(r0, r1); lv.y = pack_bf16x2(r2, r3);
            int row = arow2 + j * 16;
            uint32_t off = ((uint32_t)(row * 128 + ac * 8))
                         ^ ((uint32_t)(row & 7) << 4);
            *(uint2*)(smem + stage_off + ST_AH + off) = hv;
            *(uint2*)(smem + stage_off + ST_AL + off) = lv;
        }
    };
    // B loader via cp.async (preconverted Wc hi/lo)
    auto loadB = [&](int kc, uint32_t stage_base) {  // stage_base = sb + offset
        int k0 = kc * 64;
        #pragma unroll
        for (int j = 0; j < 8; j++) {
            int idx = j * 256 + tid;
            int sg  = idx >> 10;
            int rem = idx & 1023;
            int r = rem >> 3, c = rem & 7;
            const __nv_bfloat16* src = (sg ? g_wc_lo : g_wc_hi)
                + ((size_t)(hbase + r) * IDIM + k0 + c * 8);
            uint32_t o = (uint32_t)(r * 128 + c * 16);
            CP16(stage_base + ST_BH + (uint32_t)sg * 16384u
                 + (o ^ (uint32_t)((r & 7) << 4)), src);
        }
        CP_COMMIT();
    };

    // ldmatrix address components (128B rows, XOR swizzle)
    int arow  = warp_m * 64 + (lane & 15);
    uint32_t akoff = (uint32_t)(lane & 16);
    uint32_t axor  = (uint32_t)((lane & 7) << 4);
    int brow  = (lane & 7) + ((lane & 16) >> 1);
    uint32_t bkoff = (uint32_t)(((lane >> 3) & 1) * 16);

    uint32_t aoff[4], boff[2];
    #pragma unroll
    for (int t = 0; t < 4; t++) aoff[t] = (uint32_t)((arow + t * 16) * 128) + akoff;
    #pragma unroll
    for (int p = 0; p < 2; p++) boff[p] = (uint32_t)((warp_n * 32 + p * 16 + brow) * 128) + bkoff;

    float acc[4][4][4];
    #pragma unroll
    for (int t = 0; t < 4; t++)
        #pragma unroll
        for (int n = 0; n < 4; n++)
            #pragma unroll
            for (int c = 0; c < 4; c++) acc[t][n][c] = 0.0f;

    // ---- prologue: stage A(0), A(1) via LDG->STS; B(0), B(1) via cp.async;
    //      preload A(2) into regs for iter 0.
    ldgA(0); stsA(0u * STAGE_BYTES);
    ldgA(1); stsA(1u * STAGE_BYTES);
    loadB(0, sb + 0u * STAGE_BYTES);
    loadB(1, sb + 1u * STAGE_BYTES);
    ldgA(2);

    #pragma unroll 1
    for (int i = 0; i < 8; i++) {
        // top-of-iter: stage chunk i+2 (stage (i+2)%3, readers done at iter i-1)
        if (i + 2 < 8) {
            uint32_t stw = (uint32_t)((i + 2) % 3) * STAGE_BYTES;
            stsA(stw);
            loadB(i + 2, sb + stw);
            if (i + 3 < 8) ldgA(i + 3);
        }
        if (i + 2 < 8)      { CP_WAIT(2); }
        else if (i + 1 < 8) { CP_WAIT(1); }
        else                { CP_WAIT(0); }
        __syncthreads();

        uint32_t stb = sb + (uint32_t)(i % 3) * STAGE_BYTES;
        uint32_t AH = stb + ST_AH, AL = stb + ST_AL;
        uint32_t BH = stb + ST_BH, BL = stb + ST_BL;

        #pragma unroll
        for (int q = 0; q < 4; q++) {
            uint32_t qb = (uint32_t)(q * 32);
            uint32_t aH[4][4], aL[4][4], bH[2][4], bL[2][4];
            #pragma unroll
            for (int t = 0; t < 4; t++) {
                LDSM4(aH[t], AH + ((aoff[t] + qb) ^ axor));
                LDSM4(aL[t], AL + ((aoff[t] + qb) ^ axor));
            }
            #pragma unroll
            for (int p = 0; p < 2; p++) {
                LDSM4(bH[p], BH + ((boff[p] + qb) ^ axor));
                LDSM4(bL[p], BL + ((boff[p] + qb) ^ axor));
            }
            #pragma unroll
            for (int t = 0; t < 4; t++)
                #pragma unroll
                for (int nt = 0; nt < 4; nt++) {
                    int p  = nt >> 1;
                    int r0 = (nt & 1) * 2;
                    MMA16816(acc[t][nt], aH[t], bH[p][r0], bH[p][r0 + 1]);
                    MMA16816(acc[t][nt], aH[t], bL[p][r0], bL[p][r0 + 1]);
                    MMA16816(acc[t][nt], aL[t], bH[p][r0], bH[p][r0 + 1]);
                }
        }
        __syncthreads();
    }

    // ---- epilogue: att[s] += sum_h V[h]*tanh(acc + hb[h])
    float rowsum[8];
    #pragma unroll
    for (int r = 0; r < 8; r++) rowsum[r] = 0.0f;
    #pragma unroll
    for (int t = 0; t < 4; t++) {
        #pragma unroll
        for (int nt = 0; nt < 4; nt++) {
            int hh = warp_n * 32 + nt * 8 + tg * 2;
            float v0 = sV[hh], v1 = sV[hh + 1];
            float h0 = sHB[hh], h1 = sHB[hh + 1];
            float* c = acc[t][nt];
            rowsum[t * 2 + 0] += v0 * tanhf(c[0] + h0) + v1 * tanhf(c[1] + h1);
            rowsum[t * 2 + 1] += v0 * tanhf(c[2] + h0) + v1 * tanhf(c[3] + h1);
        }
    }
    #pragma unroll
    for (int r = 0; r < 8; r++) {
        float s = rowsum[r];
        s += __shfl_xor_sync(0xffffffffu, s, 1);
        s += __shfl_xor_sync(0xffffffffu, s, 2);
        if (tg == 0) {
            int row = warp_m * 64 + (r >> 1) * 16 + (r & 1) * 8 + g;
            atomicAdd(&attred[row], s);
        }
    }
    __syncthreads();
    if (tid < 128) atomicAdd(&g_att[b * SDIM + s0 + tid], attred[tid]);
}

// ---------------------------------------------------------------------------
// K3: masked softmax over S per batch -> alpha
// ---------------------------------------------------------------------------
__device__ __forceinline__ bool mask_at(const unsigned char* m, int idx, int is_byte) {
    if (is_byte) return m[idx] != 0;
    return ((const int*)m)[idx] != 0;
}

__global__ void k3_softmax(const unsigned char* __restrict__ mraw,
                           float* __restrict__ alpha) {
    __shared__ float red[256];
    int b = blockIdx.x;
    int tid = threadIdx.x;
    int is_byte = g_mask_is_byte;
    const float NEG_INF = __int_as_float(0xff800000);

    float lmax = NEG_INF;
    for (int s = tid; s < SDIM; s += 256)
        if (!mask_at(mraw, b * SDIM + s, is_byte))
            lmax = fmaxf(lmax, g_att[b * SDIM + s]);
    red[tid] = lmax;
    __syncthreads();
    for (int o = 128; o > 0; o >>= 1) {
        if (tid < o) red[tid] = fmaxf(red[tid], red[tid + o]);
        __syncthreads();
    }
    float smax = red[0];
    __syncthreads();

    float lsum = 0.0f;
    for (int s = tid; s < SDIM; s += 256) {
        float e = 0.0f;
        if (!mask_at(mraw, b * SDIM + s, is_byte))
            e = expf(g_att[b * SDIM + s] - smax);
        alpha[b * SDIM + s] = e;
        lsum += e;
    }
    red[tid] = lsum;
    __syncthreads();
    for (int o = 128; o > 0; o >>= 1) {
        if (tid < o) red[tid] += red[tid + o];
        __syncthreads();
    }
    float inv = 1.0f / red[0];
    __syncthreads();

    for (int s = tid; s < SDIM; s += 256)
        alpha[b * SDIM + s] *= inv;
}

// ---------------------------------------------------------------------------
// K4: cbar[b,i] = sum_s alpha[b,s] * context[b,s,i]
// ---------------------------------------------------------------------------
__global__ void k4_cbar(const float* __restrict__ context,
                        const float* __restrict__ alpha) {
    __shared__ float sal[128];
    int b  = blockIdx.y;
    int s0 = blockIdx.x * 128;
    int i  = threadIdx.x;
    if (i < 128) sal[i] = alpha[b * SDIM + s0 + i];
    __syncthreads();
    const float* cp = context + (size_t)b * SDIM * IDIM + (size_t)s0 * IDIM + i;
    float acc = 0.0f;
    #pragma unroll 4
    for (int s = 0; s < 128; s++) acc += sal[s] * cp[(size_t)s * IDIM];
    atomicAdd(&g_cbar[b * IDIM + i], acc);
}

// ---------------------------------------------------------------------------
// K5: hidden = Wc @ cbar + bc  (coalesced warp-per-row)
// ---------------------------------------------------------------------------
__global__ void __launch_bounds__(256) k5_out(const float* __restrict__ Wc,
                                              const float* __restrict__ bc,
                                              float* __restrict__ out) {
    __shared__ float sc[IDIM];
    int b  = blockIdx.x >> 2;
    int hq = blockIdx.x & 3;
    int tid = threadIdx.x;
    int wid = tid >> 5, lane = tid & 31;

    sc[tid] = g_cbar[b * IDIM + tid];
    sc[tid + 256] = g_cbar[b * IDIM + tid + 256];
    __syncthreads();

    const float4* s4 = (const float4*)sc;
    #pragma unroll 1
    for (int r = wid; r < 128; r += 8) {
        int h = hq * 128 + r;
        const float4* w4 = (const float4*)(Wc + (size_t)h * IDIM);
        float acc = 0.0f;
        #pragma unroll
        for (int j = 0; j < 4; j++) {
            float4 w = w4[lane + 32 * j];
            float4 s = s4[lane + 32 * j];
            acc += w.x * s.x + w.y * s.y + w.z * s.z + w.w * s.w;
        }
        #pragma unroll
        for (int o = 16; o > 0; o >>= 1) acc += __shfl_xor_sync(0xffffffffu, acc, o);
        if (lane == 0) out[b * HDIM + h] = acc + bc[h];
    }
}

// ---------------------------------------------------------------------------
extern "C" void kernel_launch(void* const* d_in, const int* in_sizes, int n_in,
                              void* d_out, int out_size) {
    const float* inp          = (const float*)d_in[0];
    const float* context      = (const float*)d_in[1];
    const unsigned char* mraw = (const unsigned char*)d_in[2];
    const float* Wl           = (const float*)d_in[3];
    const float* bl           = (const float*)d_in[4];
    const float* Wc           = (const float*)d_in[5];
    const float* bc           = (const float*)d_in[6];
    const float* Vv           = (const float*)d_in[7];

    float* out    = (float*)d_out;
    float* hidden = out;                   // [B, HID]
    float* alpha  = out + BDIM * HDIM;     // [B, S]

    cudaFuncSetAttribute(k2_att_mma, cudaFuncAttributeMaxDynamicSharedMemorySize, SMEM_K2);

    __nv_bfloat16 *wc_hi, *wc_lo;
    cudaGetSymbolAddress((void**)&wc_hi, g_wc_hi);
    cudaGetSymbolAddress((void**)&wc_lo, g_wc_lo);

    k0_detect<<<1, 256>>>(mraw);
    int n4w = HDIM * IDIM / 4;
    k_conv<<<n4w / 256, 256>>>(Wc, wc_hi, wc_lo, n4w);
    k1_hb<<<BDIM * 4, 256>>>(inp, Wl, bl, bc);
    k2_att_mma<<<BDIM * 16 * 4, 256, SMEM_K2>>>(context, Vv);
    k3_softmax<<<BDIM, 256>>>(mraw, alpha);
    k4_cbar<<<dim3(SDIM / 128, BDIM), 512>>>(context, alpha);
    k5_out<<<BDIM * 4, 256>>>(Wc, bc, hidden);
}

// round 12
// speedup vs baseline: 1.4553x; 1.2298x over previous
#include <cuda_runtime.h>
#include <cuda_bf16.h>
#include <math.h>
#include <stdint.h>

#define BDIM 64
#define SDIM 2048
#define IDIM 512
#define HDIM 512

// ---------------- device scratch (no cudaMalloc allowed) -------------------
__device__ float g_hb[BDIM * HDIM];
__device__ float g_att[BDIM * SDIM];
__device__ float g_cbar[BDIM * IDIM];
__device__ int   g_mask_is_byte;
__device__ float g_wc_t32[HDIM * IDIM];   // Wc pre-rounded to tf32

// ---------------- PTX helpers (sm_80-level only) ----------------------------
__device__ __forceinline__ uint32_t smem_u32(const void* p) {
    uint32_t a;
    asm("{ .reg .u64 t; cvta.to.shared.u64 t, %1; cvt.u32.u64 %0, t; }" : "=r"(a) : "l"(p));
    return a;
}
#define CP16(dst, src) asm volatile("cp.async.cg.shared.global [%0], [%1], 16;" :: "r"(dst), "l"(src))
#define CP_COMMIT()    asm volatile("cp.async.commit_group;" ::: "memory")
#define CP_WAIT(n)     asm volatile("cp.async.wait_group %0;" :: "n"(n) : "memory")

#define LDSM4(r, a)                                                           \
    asm volatile("ldmatrix.sync.aligned.m8n8.x4.shared.b16 {%0,%1,%2,%3}, [%4];" \
        : "=r"((r)[0]), "=r"((r)[1]), "=r"((r)[2]), "=r"((r)[3]) : "r"(a))

#define MMA_TF32(c, a, b0, b1)                                                \
    asm volatile("mma.sync.aligned.m16n8k8.row.col.f32.tf32.tf32.f32 "        \
        "{%0,%1,%2,%3},{%4,%5,%6,%7},{%8,%9},{%0,%1,%2,%3};"                  \
        : "+f"((c)[0]), "+f"((c)[1]), "+f"((c)[2]), "+f"((c)[3])              \
        : "r"((a)[0]), "r"((a)[1]), "r"((a)[2]), "r"((a)[3]), "r"(b0), "r"(b1))

#define CVT_TF32(x) asm volatile("cvt.rna.tf32.f32 %0, %1;" : "+r"(x) : "f"(__uint_as_float(x)))

// ---------------------------------------------------------------------------
// K0: detect mask storage (int32 vs uint8)
// ---------------------------------------------------------------------------
__global__ void k0_detect(const unsigned char* __restrict__ mraw) {
    __shared__ int found;
    if (threadIdx.x == 0) found = 0;
    __syncthreads();
    int acc = 0;
    for (int i = threadIdx.x; i < 4096; i += 256)
        if ((i & 3) != 0 && mraw[i] != 0) acc = 1;
    if (acc) atomicOr(&found, 1);
    __syncthreads();
    if (threadIdx.x == 0) g_mask_is_byte = found;
}

// ---------------------------------------------------------------------------
// KcB: Wc fp32 -> tf32-rounded fp32 (tiny: 1 MB)
// ---------------------------------------------------------------------------
__global__ void k_convB(const float* __restrict__ src, float* __restrict__ dst, int n4) {
    int i = blockIdx.x * blockDim.x + threadIdx.x;
    if (i >= n4) return;
    float4 v = ((const float4*)src)[i];
    uint4 o;
    o.x = __float_as_uint(v.x); CVT_TF32(o.x);
    o.y = __float_as_uint(v.y); CVT_TF32(o.y);
    o.z = __float_as_uint(v.z); CVT_TF32(o.z);
    o.w = __float_as_uint(v.w); CVT_TF32(o.w);
    ((uint4*)dst)[i] = o;
}

// ---------------------------------------------------------------------------
// K1: hb = inp@Wl.T + bl + bc ; zero g_cbar and g_att (warp-per-row, coalesced)
// ---------------------------------------------------------------------------
__global__ void __launch_bounds__(256) k1_hb(const float* __restrict__ inp,
                                             const float* __restrict__ Wl,
                                             const float* __restrict__ bl,
                                             const float* __restrict__ bc) {
    __shared__ float sin[IDIM];
    int b  = blockIdx.x >> 2;
    int hq = blockIdx.x & 3;
    int tid = threadIdx.x;
    int wid = tid >> 5, lane = tid & 31;

    sin[tid] = inp[b * IDIM + tid];
    sin[tid + 256] = inp[b * IDIM + tid + 256];
    g_att[b * SDIM + hq * 512 + tid * 2 + 0] = 0.0f;
    g_att[b * SDIM + hq * 512 + tid * 2 + 1] = 0.0f;
    if (tid < 128) g_cbar[b * IDIM + hq * 128 + tid] = 0.0f;
    __syncthreads();

    const float4* s4 = (const float4*)sin;
    #pragma unroll 1
    for (int r = wid; r < 128; r += 8) {
        int h = hq * 128 + r;
        const float4* w4 = (const float4*)(Wl + (size_t)h * IDIM);
        float acc = 0.0f;
        #pragma unroll
        for (int j = 0; j < 4; j++) {
            float4 w = w4[lane + 32 * j];
            float4 s = s4[lane + 32 * j];
            acc += w.x * s.x + w.y * s.y + w.z * s.z + w.w * s.w;
        }
        #pragma unroll
        for (int o = 16; o > 0; o >>= 1) acc += __shfl_xor_sync(0xffffffffu, acc, o);
        if (lane == 0) g_hb[b * HDIM + h] = acc + bl[h] + bc[h];
    }
}

// ---------------------------------------------------------------------------
// K2: single-term TF32 GEMM + tanh + V reduction.
// A = raw fp32 context via cp.async (cvt.rna applied on fragments);
// B = tf32-pre-rounded Wc via cp.async.
// CTA tile 128(s) x 128(h); K=512 in 16 chunks of 32; 3 stages x 32KB = 96KB
// -> 2 CTAs/SM. 8 warps, warp tile 64x32.
// grid = B * 16(stile) * 4(htile) = 4096 CTAs, 256 threads.
// ---------------------------------------------------------------------------
#define BK 32
#define ST_A 0u
#define ST_B 16384u
#define STAGE_BYTES 32768u
#define SMEM_K2 (3 * STAGE_BYTES)
#define NCHUNK (IDIM / BK)   // 16

__global__ void __launch_bounds__(256, 2) k2_att_mma(const float* __restrict__ context,
                                                     const float* __restrict__ Vv) {
    extern __shared__ char smem[];
    __shared__ float sV[128], sHB[128], attred[128];
    uint32_t sb = smem_u32(smem);

    int tid  = threadIdx.x;
    int wid  = tid >> 5;
    int lane = tid & 31;
    int g    = lane >> 2;
    int tg   = lane & 3;
    int warp_m = wid & 1;
    int warp_n = wid >> 1;

    int bx = blockIdx.x;
    int b     = bx >> 6;
    int stile = (bx >> 2) & 15;
    int htile = bx & 3;
    int s0    = stile * 128;
    int hbase = htile * 128;
    int bb    = b * SDIM;

    if (tid < 128) {
        sV[tid]  = Vv[hbase + tid];
        sHB[tid] = g_hb[b * HDIM + hbase + tid];
        attred[tid] = 0.0f;
    }

    // chunk loader: A 128 rows x 128B, B 128 rows x 128B, both cp.async
    const float* actx = context + (size_t)(bb + s0) * IDIM;
    auto loadAB = [&](int kc, uint32_t stage_base) {
        int k0 = kc * BK;
        #pragma unroll
        for (int j = 0; j < 4; j++) {            // A: 1024 x 16B
            int idx = j * 256 + tid;
            int r = idx >> 3, c = idx & 7;
            const float* src = actx + (size_t)r * IDIM + k0 + c * 4;
            uint32_t o = (uint32_t)(r * 128 + c * 16);
            CP16(stage_base + ST_A + (o ^ (uint32_t)((r & 7) << 4)), src);
        }
        #pragma unroll
        for (int j = 0; j < 4; j++) {            // B: 1024 x 16B
            int idx = j * 256 + tid;
            int r = idx >> 3, c = idx & 7;
            const float* src = g_wc_t32 + (size_t)(hbase + r) * IDIM + k0 + c * 4;
            uint32_t o = (uint32_t)(r * 128 + c * 16);
            CP16(stage_base + ST_B + (o ^ (uint32_t)((r & 7) << 4)), src);
        }
        CP_COMMIT();
    };

    // ldmatrix (b16-reinterpret trick for tf32): per thread
    //   quad = lane>>3 selects [row +0/+8][col-bytes +0/+16]
    int rbase = (lane & 7) + ((lane >> 3) & 1) * 8;
    uint32_t qcol = (uint32_t)(((lane >> 4) & 1) * 16);
    uint32_t sxor = (uint32_t)((lane & 7) << 4);

    uint32_t aoff[4], boff[2];
    #pragma unroll
    for (int t = 0; t < 4; t++)
        aoff[t] = (uint32_t)((warp_m * 64 + t * 16 + rbase) * 128) + qcol;
    #pragma unroll
    for (int p = 0; p < 2; p++)
        boff[p] = (uint32_t)((warp_n * 32 + p * 16 + rbase) * 128) + qcol;

    float acc[4][4][4];
    #pragma unroll
    for (int t = 0; t < 4; t++)
        #pragma unroll
        for (int n = 0; n < 4; n++)
            #pragma unroll
            for (int c = 0; c < 4; c++) acc[t][n][c] = 0.0f;

    // ---- prologue
    loadAB(0, sb + 0u * STAGE_BYTES);
    loadAB(1, sb + 1u * STAGE_BYTES);

    #pragma unroll 1
    for (int i = 0; i < NCHUNK; i++) {
        if (i + 2 < NCHUNK)
            loadAB(i + 2, sb + (uint32_t)((i + 2) % 3) * STAGE_BYTES);
        if (i + 2 < NCHUNK)      { CP_WAIT(2); }
        else if (i + 1 < NCHUNK) { CP_WAIT(1); }
        else                     { CP_WAIT(0); }
        __syncthreads();

        uint32_t stb = sb + (uint32_t)(i % 3) * STAGE_BYTES;
        uint32_t Abase = stb + ST_A, Bbase = stb + ST_B;

        #pragma unroll
        for (int s = 0; s < 4; s++) {            // 4 k8-steps per 32-chunk
            uint32_t so = (uint32_t)(s * 32);
            uint32_t afr[4][4], bfr[2][4];
            #pragma unroll
            for (int t = 0; t < 4; t++) {
                LDSM4(afr[t], Abase + ((aoff[t] + so) ^ sxor));
                CVT_TF32(afr[t][0]); CVT_TF32(afr[t][1]);
                CVT_TF32(afr[t][2]); CVT_TF32(afr[t][3]);
            }
            #pragma unroll
            for (int p = 0; p < 2; p++)
                LDSM4(bfr[p], Bbase + ((boff[p] + so) ^ sxor));
            #pragma unroll
            for (int t = 0; t < 4; t++)
                #pragma unroll
                for (int nt = 0; nt < 4; nt++) {
                    int p = nt >> 1;
                    int r0 = nt & 1;             // (b0,b1) = (bfr[p][r0], bfr[p][r0+2])
                    MMA_TF32(acc[t][nt], afr[t], bfr[p][r0], bfr[p][r0 + 2]);
                }
        }
        __syncthreads();
    }

    // ---- epilogue: att[s] += sum_h V[h]*tanh(acc + hb[h])
    float rowsum[8];
    #pragma unroll
    for (int r = 0; r < 8; r++) rowsum[r] = 0.0f;
    #pragma unroll
    for (int t = 0; t < 4; t++) {
        #pragma unroll
        for (int nt = 0; nt < 4; nt++) {
            int hh = warp_n * 32 + nt * 8 + tg * 2;
            float v0 = sV[hh], v1 = sV[hh + 1];
            float h0 = sHB[hh], h1 = sHB[hh + 1];
            float* c = acc[t][nt];
            rowsum[t * 2 + 0] += v0 * tanhf(c[0] + h0) + v1 * tanhf(c[1] + h1);
            rowsum[t * 2 + 1] += v0 * tanhf(c[2] + h0) + v1 * tanhf(c[3] + h1);
        }
    }
    #pragma unroll
    for (int r = 0; r < 8; r++) {
        float s = rowsum[r];
        s += __shfl_xor_sync(0xffffffffu, s, 1);
        s += __shfl_xor_sync(0xffffffffu, s, 2);
        if (tg == 0) {
            int row = warp_m * 64 + (r >> 1) * 16 + (r & 1) * 8 + g;
            atomicAdd(&attred[row], s);
        }
    }
    __syncthreads();
    if (tid < 128) atomicAdd(&g_att[b * SDIM + s0 + tid], attred[tid]);
}

// ---------------------------------------------------------------------------
// K3: masked softmax over S per batch -> alpha
// ---------------------------------------------------------------------------
__device__ __forceinline__ bool mask_at(const unsigned char* m, int idx, int is_byte) {
    if (is_byte) return m[idx] != 0;
    return ((const int*)m)[idx] != 0;
}

__global__ void k3_softmax(const unsigned char* __restrict__ mraw,
                           float* __restrict__ alpha) {
    __shared__ float red[256];
    int b = blockIdx.x;
    int tid = threadIdx.x;
    int is_byte = g_mask_is_byte;
    const float NEG_INF = __int_as_float(0xff800000);

    float lmax = NEG_INF;
    for (int s = tid; s < SDIM; s += 256)
        if (!mask_at(mraw, b * SDIM + s, is_byte))
            lmax = fmaxf(lmax, g_att[b * SDIM + s]);
    red[tid] = lmax;
    __syncthreads();
    for (int o = 128; o > 0; o >>= 1) {
        if (tid < o) red[tid] = fmaxf(red[tid], red[tid + o]);
        __syncthreads();
    }
    float smax = red[0];
    __syncthreads();

    float lsum = 0.0f;
    for (int s = tid; s < SDIM; s += 256) {
        float e = 0.0f;
        if (!mask_at(mraw, b * SDIM + s, is_byte))
            e = expf(g_att[b * SDIM + s] - smax);
        alpha[b * SDIM + s] = e;
        lsum += e;
    }
    red[tid] = lsum;
    __syncthreads();
    for (int o = 128; o > 0; o >>= 1) {
        if (tid < o) red[tid] += red[tid + o];
        __syncthreads();
    }
    float inv = 1.0f / red[0];
    __syncthreads();

    for (int s = tid; s < SDIM; s += 256)
        alpha[b * SDIM + s] *= inv;
}

// ---------------------------------------------------------------------------
// K4: cbar[b,i] = sum_s alpha[b,s] * context[b,s,i]
// ---------------------------------------------------------------------------
__global__ void k4_cbar(const float* __restrict__ context,
                        const float* __restrict__ alpha) {
    __shared__ float sal[128];
    int b  = blockIdx.y;
    int s0 = blockIdx.x * 128;
    int i  = threadIdx.x;
    if (i < 128) sal[i] = alpha[b * SDIM + s0 + i];
    __syncthreads();
    const float* cp = context + (size_t)b * SDIM * IDIM + (size_t)s0 * IDIM + i;
    float acc = 0.0f;
    #pragma unroll 4
    for (int s = 0; s < 128; s++) acc += sal[s] * cp[(size_t)s * IDIM];
    atomicAdd(&g_cbar[b * IDIM + i], acc);
}

// ---------------------------------------------------------------------------
// K5: hidden = Wc @ cbar + bc  (coalesced warp-per-row)
// ---------------------------------------------------------------------------
__global__ void __launch_bounds__(256) k5_out(const float* __restrict__ Wc,
                                              const float* __restrict__ bc,
                                              float* __restrict__ out) {
    __shared__ float sc[IDIM];
    int b  = blockIdx.x >> 2;
    int hq = blockIdx.x & 3;
    int tid = threadIdx.x;
    int wid = tid >> 5, lane = tid & 31;

    sc[tid] = g_cbar[b * IDIM + tid];
    sc[tid + 256] = g_cbar[b * IDIM + tid + 256];
    __syncthreads();

    const float4* s4 = (const float4*)sc;
    #pragma unroll 1
    for (int r = wid; r < 128; r += 8) {
        int h = hq * 128 + r;
        const float4* w4 = (const float4*)(Wc + (size_t)h * IDIM);
        float acc = 0.0f;
        #pragma unroll
        for (int j = 0; j < 4; j++) {
            float4 w = w4[lane + 32 * j];
            float4 s = s4[lane + 32 * j];
            acc += w.x * s.x + w.y * s.y + w.z * s.z + w.w * s.w;
        }
        #pragma unroll
        for (int o = 16; o > 0; o >>= 1) acc += __shfl_xor_sync(0xffffffffu, acc, o);
        if (lane == 0) out[b * HDIM + h] = acc + bc[h];
    }
}

// ---------------------------------------------------------------------------
extern "C" void kernel_launch(void* const* d_in, const int* in_sizes, int n_in,
                              void* d_out, int out_size) {
    const float* inp          = (const float*)d_in[0];
    const float* context      = (const float*)d_in[1];
    const unsigned char* mraw = (const unsigned char*)d_in[2];
    const float* Wl           = (const float*)d_in[3];
    const float* bl           = (const float*)d_in[4];
    const float* Wc           = (const float*)d_in[5];
    const float* bc           = (const float*)d_in[6];
    const float* Vv           = (const float*)d_in[7];

    float* out    = (float*)d_out;
    float* hidden = out;                   // [B, HID]
    float* alpha  = out + BDIM * HDIM;     // [B, S]

    cudaFuncSetAttribute(k2_att_mma, cudaFuncAttributeMaxDynamicSharedMemorySize, SMEM_K2);

    float* wc_t32;
    cudaGetSymbolAddress((void**)&wc_t32, g_wc_t32);

    k0_detect<<<1, 256>>>(mraw);
    int n4w = HDIM * IDIM / 4;
    k_convB<<<n4w / 256, 256>>>(Wc, wc_t32, n4w);
    k1_hb<<<BDIM * 4, 256>>>(inp, Wl, bl, bc);
    k2_att_mma<<<BDIM * 16 * 4, 256, SMEM_K2>>>(context, Vv);
    k3_softmax<<<BDIM, 256>>>(mraw, alpha);
    k4_cbar<<<dim3(SDIM / 128, BDIM), 512>>>(context, alpha);
    k5_out<<<BDIM * 4, 256>>>(Wc, bc, hidden);
}